// round 1
// baseline (speedup 1.0000x reference)
#include <cuda_runtime.h>
#include <math.h>

#define BDIM 4
#define CDIM 256
#define NDIM 4096

// Scratch for projected Q (B,N,C), K (B,C,N), V (B,C,N)
__device__ float g_Q[BDIM * NDIM * CDIM];
__device__ float g_K[BDIM * CDIM * NDIM];
__device__ float g_V[BDIM * CDIM * NDIM];

// ---------------------------------------------------------------------------
// Projection kernel: out = W(256x256) @ X(256x4096) + bias, per batch, for
// Wq/Wk/Wv. Q is stored transposed as (B,N,C); K,V as (B,C,N).
// Tile 64(o) x 64(n), 256 threads, 4x4 per thread, k-chunk 16.
// ---------------------------------------------------------------------------
__global__ __launch_bounds__(256) void proj_kernel(
    const float* __restrict__ x,
    const float* __restrict__ Wq, const float* __restrict__ bq,
    const float* __restrict__ Wk, const float* __restrict__ bk,
    const float* __restrict__ Wv, const float* __restrict__ bv)
{
    __shared__ float w_s[16][68];   // [kk][o], padded row
    __shared__ float x_s[16][64];   // [kk][n]

    const int n0 = blockIdx.x * 64;
    const int o0 = blockIdx.y * 64;
    const int b     = blockIdx.z / 3;
    const int which = blockIdx.z % 3;
    const float* W    = (which == 0) ? Wq : (which == 1) ? Wk : Wv;
    const float* bias = (which == 0) ? bq : (which == 1) ? bk : bv;

    const int t  = threadIdx.x;
    const int tx = t & 15;
    const int ty = t >> 4;

    const float* xb = x + (size_t)b * CDIM * NDIM;

    float acc[4][4];
    #pragma unroll
    for (int i = 0; i < 4; i++)
        #pragma unroll
        for (int j = 0; j < 4; j++) acc[i][j] = 0.f;

    const int lo = t >> 2;          // 0..63   W-tile row (o)
    const int lc = (t & 3) << 2;    // 0,4,8,12 W-tile col chunk (c)
    const int xr = t >> 4;          // 0..15   X-tile row (c)
    const int xn = (t & 15) << 2;   // X-tile col chunk (n)

    for (int c0 = 0; c0 < CDIM; c0 += 16) {
        float4 wv4 = *(const float4*)&W[(size_t)(o0 + lo) * CDIM + c0 + lc];
        float4 xv4 = *(const float4*)&xb[(size_t)(c0 + xr) * NDIM + n0 + xn];
        __syncthreads();
        w_s[lc + 0][lo] = wv4.x;
        w_s[lc + 1][lo] = wv4.y;
        w_s[lc + 2][lo] = wv4.z;
        w_s[lc + 3][lo] = wv4.w;
        *(float4*)&x_s[xr][xn] = xv4;
        __syncthreads();
        #pragma unroll
        for (int kk = 0; kk < 16; kk++) {
            float4 a4 = *(const float4*)&w_s[kk][ty << 2];
            float4 b4 = *(const float4*)&x_s[kk][tx << 2];
            float a[4] = {a4.x, a4.y, a4.z, a4.w};
            float bb[4] = {b4.x, b4.y, b4.z, b4.w};
            #pragma unroll
            for (int i = 0; i < 4; i++)
                #pragma unroll
                for (int j = 0; j < 4; j++)
                    acc[i][j] = fmaf(a[i], bb[j], acc[i][j]);
        }
    }

    float bo[4];
    #pragma unroll
    for (int i = 0; i < 4; i++) bo[i] = bias[o0 + (ty << 2) + i];

    if (which == 0) {
        // Q stored (B, N, C): q[b][n][o]
        #pragma unroll
        for (int i = 0; i < 4; i++)
            #pragma unroll
            for (int j = 0; j < 4; j++) {
                int n = n0 + (tx << 2) + j;
                int o = o0 + (ty << 2) + i;
                g_Q[((size_t)b * NDIM + n) * CDIM + o] = acc[i][j] + bo[i];
            }
    } else {
        float* dst = (which == 1) ? g_K : g_V;
        #pragma unroll
        for (int i = 0; i < 4; i++)
            #pragma unroll
            for (int j = 0; j < 4; j++) {
                int n = n0 + (tx << 2) + j;
                int o = o0 + (ty << 2) + i;
                dst[((size_t)b * CDIM + o) * NDIM + n] = acc[i][j] + bo[i];
            }
    }
}

// ---------------------------------------------------------------------------
// Fused flash-attention kernel.
// One CTA = 64 query rows of one batch. Loops over 64-key tiles:
//   S(64x64) = Q_tile(64x256) @ K_tile(256x64)   (k-chunked through smem)
//   online softmax (row state m,l replicated across the 16 tx-threads of a row)
//   O(64x256) += P(64x64) @ V_tile(64x256)^T     (P and V staged in smem)
// Thread map: 16x16 threads. S: thread owns rows 4ty..+3, cols 4tx..+3.
//             O: thread owns rows 4ty..+3, channels 16tx..+15.
// ---------------------------------------------------------------------------
#define ATTN_SMEM_FLOATS (1088 + 1024 + 4160 + 16640)   // q_s,k_s,p_s,v_s
#define ATTN_SMEM_BYTES  (ATTN_SMEM_FLOATS * 4)         // 91648 B

__global__ __launch_bounds__(256, 2) void attn_kernel(float* __restrict__ out)
{
    extern __shared__ float sm[];
    float* q_s = sm;                 // [16][68]  (kk, r) padded
    float* k_s = sm + 1088;          // [16][64]  (kk, m)
    float* p_s = sm + 2112;          // [64][65]  (r, m) padded
    float* v_s = sm + 6272;          // [64][260] (m, c) padded

    const int b  = blockIdx.y;
    const int n0 = blockIdx.x * 64;
    const int t  = threadIdx.x;
    const int tx = t & 15;
    const int ty = t >> 4;

    const float* Qb = g_Q + (size_t)b * NDIM * CDIM;
    const float* Kb = g_K + (size_t)b * CDIM * NDIM;
    const float* Vb = g_V + (size_t)b * CDIM * NDIM;

    float O[4][16];
    #pragma unroll
    for (int i = 0; i < 4; i++)
        #pragma unroll
        for (int c = 0; c < 16; c++) O[i][c] = 0.f;

    float mrow[4], lrow[4];
    #pragma unroll
    for (int i = 0; i < 4; i++) { mrow[i] = -INFINITY; lrow[i] = 0.f; }

    const int qr = t >> 2;          // 0..63  Q-tile row
    const int qc = (t & 3) << 2;    //        Q-tile col chunk (kk)
    const int kr = t >> 4;          // 0..15  K-tile row (kk)
    const int km = (t & 15) << 2;   //        K-tile col chunk (m)

    for (int m0 = 0; m0 < NDIM; m0 += 64) {
        // ---- S = Q @ K -------------------------------------------------
        float S[4][4];
        #pragma unroll
        for (int i = 0; i < 4; i++)
            #pragma unroll
            for (int j = 0; j < 4; j++) S[i][j] = 0.f;

        for (int c0 = 0; c0 < CDIM; c0 += 16) {
            float4 qv = *(const float4*)&Qb[(size_t)(n0 + qr) * CDIM + c0 + qc];
            float4 kv = *(const float4*)&Kb[(size_t)(c0 + kr) * NDIM + m0 + km];
            __syncthreads();
            q_s[(qc + 0) * 68 + qr] = qv.x;
            q_s[(qc + 1) * 68 + qr] = qv.y;
            q_s[(qc + 2) * 68 + qr] = qv.z;
            q_s[(qc + 3) * 68 + qr] = qv.w;
            *(float4*)&k_s[kr * 64 + km] = kv;
            __syncthreads();
            #pragma unroll
            for (int kk = 0; kk < 16; kk++) {
                float4 a4 = *(const float4*)&q_s[kk * 68 + (ty << 2)];
                float4 b4 = *(const float4*)&k_s[kk * 64 + (tx << 2)];
                float a[4] = {a4.x, a4.y, a4.z, a4.w};
                float bb[4] = {b4.x, b4.y, b4.z, b4.w};
                #pragma unroll
                for (int i = 0; i < 4; i++)
                    #pragma unroll
                    for (int j = 0; j < 4; j++)
                        S[i][j] = fmaf(a[i], bb[j], S[i][j]);
            }
        }

        // ---- online softmax -------------------------------------------
        #pragma unroll
        for (int i = 0; i < 4; i++) {
            float rmax = fmaxf(fmaxf(S[i][0], S[i][1]), fmaxf(S[i][2], S[i][3]));
            #pragma unroll
            for (int s = 8; s > 0; s >>= 1)
                rmax = fmaxf(rmax, __shfl_xor_sync(0xffffffffu, rmax, s));
            float mnew = fmaxf(mrow[i], rmax);
            float corr = __expf(mrow[i] - mnew);   // exp(-inf)=0 on first tile
            float rsum = 0.f;
            #pragma unroll
            for (int j = 0; j < 4; j++) {
                S[i][j] = __expf(S[i][j] - mnew);
                rsum += S[i][j];
            }
            #pragma unroll
            for (int s = 8; s > 0; s >>= 1)
                rsum += __shfl_xor_sync(0xffffffffu, rsum, s);
            lrow[i] = lrow[i] * corr + rsum;
            mrow[i] = mnew;
            #pragma unroll
            for (int c = 0; c < 16; c++) O[i][c] *= corr;
        }

        // ---- stage P and V tiles --------------------------------------
        // (prior O-update readers of p_s/v_s all passed the S-loop barriers)
        #pragma unroll
        for (int i = 0; i < 4; i++)
            #pragma unroll
            for (int j = 0; j < 4; j++)
                p_s[((ty << 2) + i) * 65 + (tx << 2) + j] = S[i][j];
        {
            const float* vrow = &Vb[(size_t)t * NDIM + m0];  // channel = t
            #pragma unroll
            for (int j4 = 0; j4 < 16; j4++) {
                float4 vv = *(const float4*)&vrow[4 * j4];
                v_s[(4 * j4 + 0) * 260 + t] = vv.x;
                v_s[(4 * j4 + 1) * 260 + t] = vv.y;
                v_s[(4 * j4 + 2) * 260 + t] = vv.z;
                v_s[(4 * j4 + 3) * 260 + t] = vv.w;
            }
        }
        __syncthreads();

        // ---- O += P @ V^T ---------------------------------------------
        #pragma unroll 4
        for (int m = 0; m < 64; m++) {
            float p0 = p_s[((ty << 2) + 0) * 65 + m];
            float p1 = p_s[((ty << 2) + 1) * 65 + m];
            float p2 = p_s[((ty << 2) + 2) * 65 + m];
            float p3 = p_s[((ty << 2) + 3) * 65 + m];
            const float* vr = &v_s[m * 260 + (tx << 4)];
            #pragma unroll
            for (int q4 = 0; q4 < 4; q4++) {
                float4 v4 = *(const float4*)&vr[4 * q4];
                float vv[4] = {v4.x, v4.y, v4.z, v4.w};
                #pragma unroll
                for (int e = 0; e < 4; e++) {
                    int c = 4 * q4 + e;
                    O[0][c] = fmaf(p0, vv[e], O[0][c]);
                    O[1][c] = fmaf(p1, vv[e], O[1][c]);
                    O[2][c] = fmaf(p2, vv[e], O[2][c]);
                    O[3][c] = fmaf(p3, vv[e], O[3][c]);
                }
            }
        }
        __syncthreads();
    }

    // ---- epilogue: normalize + store out (B, C, N) --------------------
    #pragma unroll
    for (int i = 0; i < 4; i++) {
        float inv = 1.f / lrow[i];
        int n = n0 + (ty << 2) + i;
        #pragma unroll
        for (int c = 0; c < 16; c++) {
            int ch = (tx << 4) + c;
            out[((size_t)b * CDIM + ch) * NDIM + n] = O[i][c] * inv;
        }
    }
}

// ---------------------------------------------------------------------------
extern "C" void kernel_launch(void* const* d_in, const int* in_sizes, int n_in,
                              void* d_out, int out_size)
{
    const float* x  = (const float*)d_in[0];
    const float* Wq = (const float*)d_in[1];
    const float* bq = (const float*)d_in[2];
    const float* Wk = (const float*)d_in[3];
    const float* bk = (const float*)d_in[4];
    const float* Wv = (const float*)d_in[5];
    const float* bv = (const float*)d_in[6];
    float* out = (float*)d_out;

    cudaFuncSetAttribute(attn_kernel,
                         cudaFuncAttributeMaxDynamicSharedMemorySize,
                         ATTN_SMEM_BYTES);

    dim3 pg(NDIM / 64, CDIM / 64, BDIM * 3);
    proj_kernel<<<pg, 256>>>(x, Wq, bq, Wk, bk, Wv, bv);

    dim3 ag(NDIM / 64, BDIM);
    attn_kernel<<<ag, 256, ATTN_SMEM_BYTES>>>(out);
}

// round 4
// speedup vs baseline: 1.7538x; 1.7538x over previous
#include <cuda_runtime.h>
#include <math.h>

#define BDIM 4
#define CDIM 256
#define NDIM 4096

#define QT 128      // queries per CTA
#define KT 64       // keys per tile
#define CCH 32      // channel chunk for K staging

typedef unsigned long long u64;

// Scratch for projected Q (B,N,C), K (B,C,N), V (B,C,N)
__device__ float g_Q[BDIM * NDIM * CDIM];
__device__ float g_K[BDIM * CDIM * NDIM];
__device__ float g_V[BDIM * CDIM * NDIM];

// ---- packed f32x2 helpers (sm_103a FFMA2 path, PTX-only) -------------------
__device__ __forceinline__ u64 pack2(float lo, float hi) {
    u64 r; asm("mov.b64 %0, {%1, %2};" : "=l"(r) : "f"(lo), "f"(hi)); return r;
}
__device__ __forceinline__ void unpack2(u64 v, float& lo, float& hi) {
    asm("mov.b64 {%0, %1}, %2;" : "=f"(lo), "=f"(hi) : "l"(v));
}
__device__ __forceinline__ u64 fma2(u64 a, u64 b, u64 c) {
    u64 d; asm("fma.rn.f32x2 %0, %1, %2, %3;" : "=l"(d) : "l"(a), "l"(b), "l"(c));
    return d;
}
__device__ __forceinline__ u64 mul2(u64 a, u64 b) {
    u64 d; asm("mul.rn.f32x2 %0, %1, %2;" : "=l"(d) : "l"(a), "l"(b)); return d;
}

// ---------------------------------------------------------------------------
// Projection kernel: out = W(256x256) @ X(256x4096) + bias per batch, for
// Wq/Wk/Wv. Q stored (B,N,C); K,V stored (B,C,N).
// ---------------------------------------------------------------------------
__global__ __launch_bounds__(256) void proj_kernel(
    const float* __restrict__ x,
    const float* __restrict__ Wq, const float* __restrict__ bq,
    const float* __restrict__ Wk, const float* __restrict__ bk,
    const float* __restrict__ Wv, const float* __restrict__ bv)
{
    __shared__ float w_s[16][68];
    __shared__ float x_s[16][64];

    const int n0 = blockIdx.x * 64;
    const int o0 = blockIdx.y * 64;
    const int b     = blockIdx.z / 3;
    const int which = blockIdx.z % 3;
    const float* W    = (which == 0) ? Wq : (which == 1) ? Wk : Wv;
    const float* bias = (which == 0) ? bq : (which == 1) ? bk : bv;

    const int t  = threadIdx.x;
    const int tx = t & 15;
    const int ty = t >> 4;

    const float* xb = x + (size_t)b * CDIM * NDIM;

    float acc[4][4];
    #pragma unroll
    for (int i = 0; i < 4; i++)
        #pragma unroll
        for (int j = 0; j < 4; j++) acc[i][j] = 0.f;

    const int lo = t >> 2;
    const int lc = (t & 3) << 2;
    const int xr = t >> 4;
    const int xn = (t & 15) << 2;

    for (int c0 = 0; c0 < CDIM; c0 += 16) {
        float4 wv4 = *(const float4*)&W[(size_t)(o0 + lo) * CDIM + c0 + lc];
        float4 xv4 = *(const float4*)&xb[(size_t)(c0 + xr) * NDIM + n0 + xn];
        __syncthreads();
        w_s[lc + 0][lo] = wv4.x;
        w_s[lc + 1][lo] = wv4.y;
        w_s[lc + 2][lo] = wv4.z;
        w_s[lc + 3][lo] = wv4.w;
        *(float4*)&x_s[xr][xn] = xv4;
        __syncthreads();
        #pragma unroll
        for (int kk = 0; kk < 16; kk++) {
            float4 a4 = *(const float4*)&w_s[kk][ty << 2];
            float4 b4 = *(const float4*)&x_s[kk][tx << 2];
            float a[4] = {a4.x, a4.y, a4.z, a4.w};
            float bb[4] = {b4.x, b4.y, b4.z, b4.w};
            #pragma unroll
            for (int i = 0; i < 4; i++)
                #pragma unroll
                for (int j = 0; j < 4; j++)
                    acc[i][j] = fmaf(a[i], bb[j], acc[i][j]);
        }
    }

    float bo[4];
    #pragma unroll
    for (int i = 0; i < 4; i++) bo[i] = bias[o0 + (ty << 2) + i];

    if (which == 0) {
        #pragma unroll
        for (int i = 0; i < 4; i++)
            #pragma unroll
            for (int j = 0; j < 4; j++) {
                int n = n0 + (tx << 2) + j;
                int o = o0 + (ty << 2) + i;
                g_Q[((size_t)b * NDIM + n) * CDIM + o] = acc[i][j] + bo[i];
            }
    } else {
        float* dst = (which == 1) ? g_K : g_V;
        #pragma unroll
        for (int i = 0; i < 4; i++)
            #pragma unroll
            for (int j = 0; j < 4; j++) {
                int n = n0 + (tx << 2) + j;
                int o = o0 + (ty << 2) + i;
                dst[((size_t)b * CDIM + o) * NDIM + n] = acc[i][j] + bo[i];
            }
    }
}

// ---------------------------------------------------------------------------
// Fused flash-attention v2.1 (v2 + fixed epilogue store covering all 256 ch).
//   CTA = 128 query rows. Q tile persistent in SMEM (loaded once).
//   Per 64-key tile: S(128x64) via FFMA2, online softmax, O update in two
//   128-channel halves. Thread map 16x16: S: 8q x 4k; O: 8q x 16ch.
// SMEM (floats):
//   q_s [256][132] = 33792     (persistent Q, [c][q]; reused as O staging)
//   k_s [32][64]   = 2048
//   p_s [128][68]  = 8704      ([q][m])
//   v_s [64][132]  = 8448      ([m][c_local], one 128-ch half at a time)
// ---------------------------------------------------------------------------
#define QS_F (256 * 132)
#define KS_F (32 * 64)
#define PS_F (128 * 68)
#define VS_F (64 * 132)
#define ATTN_SMEM_F (QS_F + KS_F + PS_F + VS_F)
#define ATTN_SMEM_BYTES (ATTN_SMEM_F * 4)   // 211968 B

__global__ __launch_bounds__(256, 1) void attn_kernel(float* __restrict__ out)
{
    extern __shared__ float sm[];
    float* q_s = sm;
    float* k_s = sm + QS_F;
    float* p_s = k_s + KS_F;
    float* v_s = p_s + PS_F;

    const int b  = blockIdx.y;
    const int n0 = blockIdx.x * QT;
    const int t  = threadIdx.x;
    const int tx = t & 15;
    const int ty = t >> 4;

    const float* Kb0 = g_K + (size_t)b * CDIM * NDIM;
    const float* Vb0 = g_V + (size_t)b * CDIM * NDIM;

    // ---- load Q tile once: g_Q is (N,C) row-major -> q_s[c][q] ------------
    {
        const int r  = t >> 1;            // query row 0..127
        const int cb = (t & 1) * 128;     // channel half
        const float* src = g_Q + ((size_t)b * NDIM + n0 + r) * CDIM + cb;
        #pragma unroll
        for (int i = 0; i < 128; i += 4) {
            float4 v = *(const float4*)(src + i);
            q_s[(cb + i + 0) * 132 + r] = v.x;
            q_s[(cb + i + 1) * 132 + r] = v.y;
            q_s[(cb + i + 2) * 132 + r] = v.z;
            q_s[(cb + i + 3) * 132 + r] = v.w;
        }
    }

    u64 O[8][8];                         // [query][ch-pair]; pairs 0-3 half0, 4-7 half1
    #pragma unroll
    for (int i = 0; i < 8; i++)
        #pragma unroll
        for (int j = 0; j < 8; j++) O[i][j] = 0ull;

    float mrow[8], lrow[8];
    #pragma unroll
    for (int i = 0; i < 8; i++) { mrow[i] = -INFINITY; lrow[i] = 0.f; }

    for (int m0 = 0; m0 < NDIM; m0 += KT) {
        u64 Sp[4][4];                    // [q-pair][key]
        #pragma unroll
        for (int i = 0; i < 4; i++)
            #pragma unroll
            for (int j = 0; j < 4; j++) Sp[i][j] = 0ull;

        // ---- S = Q @ K ----------------------------------------------------
        for (int c0 = 0; c0 < CDIM; c0 += CCH) {
            const float* kp = Kb0 + (size_t)(c0 + (t >> 3)) * NDIM + m0 + (t & 7) * 8;
            float4 ka = ((const float4*)kp)[0];
            float4 kb = ((const float4*)kp)[1];
            __syncthreads();
            *(float4*)&k_s[(t >> 3) * 64 + (t & 7) * 8]     = ka;
            *(float4*)&k_s[(t >> 3) * 64 + (t & 7) * 8 + 4] = kb;
            __syncthreads();
            #pragma unroll 8
            for (int kk = 0; kk < CCH; kk++) {
                float4 qa = *(const float4*)&q_s[(c0 + kk) * 132 + ty * 8];
                float4 qb = *(const float4*)&q_s[(c0 + kk) * 132 + ty * 8 + 4];
                float4 kv = *(const float4*)&k_s[kk * 64 + tx * 4];
                u64 qp[4] = { pack2(qa.x, qa.y), pack2(qa.z, qa.w),
                              pack2(qb.x, qb.y), pack2(qb.z, qb.w) };
                u64 kd[4] = { pack2(kv.x, kv.x), pack2(kv.y, kv.y),
                              pack2(kv.z, kv.z), pack2(kv.w, kv.w) };
                #pragma unroll
                for (int i = 0; i < 4; i++)
                    #pragma unroll
                    for (int j = 0; j < 4; j++)
                        Sp[i][j] = fma2(qp[i], kd[j], Sp[i][j]);
            }
        }

        // ---- online softmax ----------------------------------------------
        float s[8][4];
        #pragma unroll
        for (int i = 0; i < 4; i++)
            #pragma unroll
            for (int j = 0; j < 4; j++)
                unpack2(Sp[i][j], s[2 * i][j], s[2 * i + 1][j]);

        #pragma unroll
        for (int i = 0; i < 8; i++) {
            float rmax = fmaxf(fmaxf(s[i][0], s[i][1]), fmaxf(s[i][2], s[i][3]));
            #pragma unroll
            for (int sh = 8; sh > 0; sh >>= 1)
                rmax = fmaxf(rmax, __shfl_xor_sync(0xffffffffu, rmax, sh));
            float mnew = fmaxf(mrow[i], rmax);
            float corr = __expf(mrow[i] - mnew);
            float rsum = 0.f;
            #pragma unroll
            for (int j = 0; j < 4; j++) {
                s[i][j] = __expf(s[i][j] - mnew);
                rsum += s[i][j];
            }
            #pragma unroll
            for (int sh = 8; sh > 0; sh >>= 1)
                rsum += __shfl_xor_sync(0xffffffffu, rsum, sh);
            lrow[i] = lrow[i] * corr + rsum;
            mrow[i] = mnew;
            u64 c2 = pack2(corr, corr);
            #pragma unroll
            for (int cp = 0; cp < 8; cp++) O[i][cp] = mul2(O[i][cp], c2);
        }

        // ---- stage P ([q][m]) --------------------------------------------
        #pragma unroll
        for (int i = 0; i < 8; i++)
            #pragma unroll
            for (int j = 0; j < 4; j++)
                p_s[(ty * 8 + i) * 68 + tx * 4 + j] = s[i][j];

        // ---- O += P @ V^T, two 128-channel halves ------------------------
        #pragma unroll
        for (int half = 0; half < 2; half++) {
            const float* vp = Vb0 + (size_t)(half * 128 + (t >> 1)) * NDIM
                              + m0 + (t & 1) * 32;
            float4 va[8];
            #pragma unroll
            for (int u = 0; u < 8; u++) va[u] = ((const float4*)vp)[u];
            __syncthreads();            // prior readers of v_s done; p_s visible
            {
                const int c  = t >> 1;
                const int mb = (t & 1) * 32;
                #pragma unroll
                for (int u = 0; u < 8; u++) {
                    v_s[(mb + 4 * u + 0) * 132 + c] = va[u].x;
                    v_s[(mb + 4 * u + 1) * 132 + c] = va[u].y;
                    v_s[(mb + 4 * u + 2) * 132 + c] = va[u].z;
                    v_s[(mb + 4 * u + 3) * 132 + c] = va[u].w;
                }
            }
            __syncthreads();

            const int cb = half * 4;
            #pragma unroll 2
            for (int m = 0; m < KT; m++) {
                u64 pd[8];
                #pragma unroll
                for (int i = 0; i < 8; i++) {
                    float pv = p_s[(ty * 8 + i) * 68 + m];
                    pd[i] = pack2(pv, pv);
                }
                float4 v0 = *(const float4*)&v_s[m * 132 + tx * 8];
                float4 v1 = *(const float4*)&v_s[m * 132 + tx * 8 + 4];
                u64 vpk[4] = { pack2(v0.x, v0.y), pack2(v0.z, v0.w),
                               pack2(v1.x, v1.y), pack2(v1.z, v1.w) };
                #pragma unroll
                for (int i = 0; i < 8; i++)
                    #pragma unroll
                    for (int j = 0; j < 4; j++)
                        O[i][cb + j] = fma2(pd[i], vpk[j], O[i][cb + j]);
            }
            __syncthreads();            // done reading v_s before next half restages
        }
    }

    // ---- epilogue: normalize, transpose via q_s, coalesced store ----------
    __syncthreads();                    // q_s free for reuse
    #pragma unroll
    for (int i = 0; i < 8; i++) {
        float inv = 1.f / lrow[i];
        u64 inv2 = pack2(inv, inv);
        int r = ty * 8 + i;
        #pragma unroll
        for (int cp = 0; cp < 8; cp++) {
            u64 sc = mul2(O[i][cp], inv2);
            float lo, hi;
            unpack2(sc, lo, hi);
            int ch = (cp < 4) ? (tx * 8 + 2 * cp) : (128 + tx * 8 + 2 * (cp - 4));
            q_s[(ch + 0) * 132 + r] = lo;
            q_s[(ch + 1) * 132 + r] = hi;
        }
    }
    __syncthreads();
    {
        // FIXED: one thread per channel (t = 0..255), store the full
        // 128-query row for that channel. Coalesced: row is contiguous.
        float* dst = out + ((size_t)b * CDIM + t) * NDIM + n0;
        const float* src = &q_s[t * 132];
        #pragma unroll
        for (int i = 0; i < 128; i += 4)
            *(float4*)(dst + i) = *(const float4*)(src + i);
    }
}

// ---------------------------------------------------------------------------
extern "C" void kernel_launch(void* const* d_in, const int* in_sizes, int n_in,
                              void* d_out, int out_size)
{
    const float* x  = (const float*)d_in[0];
    const float* Wq = (const float*)d_in[1];
    const float* bq = (const float*)d_in[2];
    const float* Wk = (const float*)d_in[3];
    const float* bk = (const float*)d_in[4];
    const float* Wv = (const float*)d_in[5];
    const float* bv = (const float*)d_in[6];
    float* out = (float*)d_out;

    cudaFuncSetAttribute(attn_kernel,
                         cudaFuncAttributeMaxDynamicSharedMemorySize,
                         ATTN_SMEM_BYTES);

    dim3 pg(NDIM / 64, CDIM / 64, BDIM * 3);
    proj_kernel<<<pg, 256>>>(x, Wq, bq, Wk, bk, Wv, bv);

    dim3 ag(NDIM / QT, BDIM);
    attn_kernel<<<ag, 256, ATTN_SMEM_BYTES>>>(out);
}